// round 1
// baseline (speedup 1.0000x reference)
#include <cuda_runtime.h>

// Problem shape: x is (64, 8, 32, 32) fp32. E=64 rows (1 center + 63 error terms),
// content = 8*32*32 = 8192 elements. Output = (1 + 63 + 8192) rows x 8192.
#define N_CONTENT 8192
#define E_ROWS 64

// Scratch (no device allocation allowed; __device__ globals are the sanctioned path)
__device__ float g_val[N_CONTENT];
__device__ int   g_flag[N_CONTENT];

// ---------------------------------------------------------------------------
// 1) Zero the full output with vectorized stores (output is 0xAA-poisoned).
// ---------------------------------------------------------------------------
__global__ void zero_kernel(float4* __restrict__ out, long long n4) {
    long long i = (long long)blockIdx.x * blockDim.x + threadIdx.x;
    long long stride = (long long)gridDim.x * blockDim.x;
    float4 z = make_float4(0.f, 0.f, 0.f, 0.f);
    for (; i < n4; i += stride) out[i] = z;
}

// ---------------------------------------------------------------------------
// 2) Per-element zonotope ReLU: head row, 63 body rows, and stash (delta/2, cross).
// ---------------------------------------------------------------------------
__global__ void compute_kernel(const float* __restrict__ x, float* __restrict__ out) {
    int k = blockIdx.x * blockDim.x + threadIdx.x;
    if (k >= N_CONTENT) return;

    float c = x[k];
    float err = 0.f;
#pragma unroll 9
    for (int e = 1; e < E_ROWS; e++) {
        err += fabsf(x[e * N_CONTENT + k]);   // coalesced across k, x fits in L2
    }

    float upper = c + err;
    float lower = c - err;

    float cross  = (lower * upper < 0.f) ? 1.f : 0.f;
    float nonneg = (lower >= 0.f) ? 1.f : 0.f;

    // Replicate reference exactly: lam = nonneg + cross * upper/(upper-lower),
    // NaN (e.g. 0*inf when upper==lower) -> 0.5
    float lam = nonneg + cross * (upper / (upper - lower));
    if (isnan(lam)) lam = 0.5f;

    float delta = fmaxf(-lam * lower, (1.f - lam) * upper);

    // head (row 0)
    out[k] = (delta * 0.5f + lam * c) * cross + c * nonneg;

    // body (rows 1..63): x[e] * (lam*cross + nonneg)
    float mult = lam * cross + nonneg;
#pragma unroll 9
    for (int e = 1; e < E_ROWS; e++) {
        out[e * N_CONTENT + k] = x[e * N_CONTENT + k] * mult;
    }

    g_val[k]  = delta * 0.5f;
    g_flag[k] = (cross > 0.f) ? 1 : 0;
}

// ---------------------------------------------------------------------------
// 3) Stream-compaction scatter into the tail.
//    Single block: exact (order-preserving) prefix scan of the cross flags,
//    then tail[cumsum-1][k] = delta/2 for each crossing k. Non-crossing
//    elements' clipped writes in the reference store 0 into an already-zero
//    tail => value no-ops => skipped here.
// ---------------------------------------------------------------------------
__global__ void scatter_kernel(float* __restrict__ out) {
    __shared__ int warp_sums[32];

    int tid  = threadIdx.x;          // 1024 threads
    int lane = tid & 31;
    int warp = tid >> 5;
    int base = tid * 8;              // 8 flags per thread -> 8192 total

    int flags[8];
    int local = 0;
#pragma unroll
    for (int i = 0; i < 8; i++) {
        flags[i] = g_flag[base + i];
        local += flags[i];
    }

    // warp-level inclusive scan of per-thread counts
    int v = local;
#pragma unroll
    for (int off = 1; off < 32; off <<= 1) {
        int n = __shfl_up_sync(0xffffffffu, v, off);
        if (lane >= off) v += n;
    }
    if (lane == 31) warp_sums[warp] = v;
    __syncthreads();

    // warp 0 scans the 32 warp totals (inclusive)
    if (warp == 0) {
        int w = warp_sums[lane];
#pragma unroll
        for (int off = 1; off < 32; off <<= 1) {
            int n = __shfl_up_sync(0xffffffffu, w, off);
            if (lane >= off) w += n;
        }
        warp_sums[lane] = w;
    }
    __syncthreads();

    int excl = (v - local) + (warp > 0 ? warp_sums[warp - 1] : 0);

    float* tail = out + (long long)E_ROWS * N_CONTENT;
    int row = excl;
#pragma unroll
    for (int i = 0; i < 8; i++) {
        int k = base + i;
        if (flags[i]) {
            int r = min(row, N_CONTENT - 1);   // matches jnp.clip (can't trigger, but cheap)
            tail[(long long)r * N_CONTENT + k] = g_val[k];
            row++;
        }
    }
}

// ---------------------------------------------------------------------------
extern "C" void kernel_launch(void* const* d_in, const int* in_sizes, int n_in,
                              void* d_out, int out_size) {
    const float* x = (const float*)d_in[0];
    float* out = (float*)d_out;

    // out_size = 8256 * 8192 floats; divisible by 4 -> float4 stores
    long long n4 = (long long)out_size / 4;
    zero_kernel<<<4096, 256>>>((float4*)out, n4);
    compute_kernel<<<(N_CONTENT + 255) / 256, 256>>>(x, out);
    scatter_kernel<<<1, 1024>>>(out);
}

// round 2
// speedup vs baseline: 1.0946x; 1.0946x over previous
#include <cuda_runtime.h>

// x: (64, 8, 32, 32) fp32. E=64 rows (1 center + 63 error terms),
// content = 8192 elements. Output = (1 + 63 + 8192) rows x 8192 = 270 MB.
#define N_CONTENT 8192
#define N_COL4    (N_CONTENT / 4)   // 2048
#define E_ROWS    64

// Per-k scratch (aligned for float4 access). No device allocation allowed.
__device__ float4 g_mult4[N_COL4];
__device__ float4 g_head4[N_COL4];
__device__ float  g_val[N_CONTENT];
__device__ int    g_flag[N_CONTENT];

// ---------------------------------------------------------------------------
// A) Per-k zonotope ReLU scalars: err -> lam -> mult, head value, tail value.
//    Writes only 96 KB of scratch; no big output traffic.
// ---------------------------------------------------------------------------
__global__ void precompute_kernel(const float* __restrict__ x) {
    int k = blockIdx.x * blockDim.x + threadIdx.x;
    if (k >= N_CONTENT) return;

    float c = x[k];
    float err = 0.f;
#pragma unroll 9
    for (int e = 1; e < E_ROWS; e++)
        err += fabsf(x[e * N_CONTENT + k]);     // coalesced, x (2 MB) is L2-resident

    float upper = c + err;
    float lower = c - err;

    float cross  = (lower * upper < 0.f) ? 1.f : 0.f;
    float nonneg = (lower >= 0.f) ? 1.f : 0.f;

    // Reference-exact: lam = nonneg + cross * upper/(upper-lower), NaN -> 0.5
    float lam = nonneg + cross * (upper / (upper - lower));
    if (isnan(lam)) lam = 0.5f;

    float delta = fmaxf(-lam * lower, (1.f - lam) * upper);

    ((float*)g_mult4)[k] = lam * cross + nonneg;
    ((float*)g_head4)[k] = (delta * 0.5f + lam * c) * cross + c * nonneg;
    g_val[k]  = delta * 0.5f;
    g_flag[k] = (cross > 0.f) ? 1 : 0;
}

// ---------------------------------------------------------------------------
// B1) Head + body rows (64 x 8192 = 2 MB), float4 per thread, single write.
//     row 0: head[k];  rows 1..63: x[e][k] * mult[k]
// ---------------------------------------------------------------------------
__global__ void headbody_kernel(const float4* __restrict__ x4, float4* __restrict__ out4) {
    int i = blockIdx.x * blockDim.x + threadIdx.x;   // 0 .. 64*2048-1
    int row = i >> 11;
    int c4  = i & (N_COL4 - 1);

    if (row == 0) {
        out4[i] = g_head4[c4];
    } else {
        float4 v = x4[i];        // L2-resident
        float4 m = g_mult4[c4];
        v.x *= m.x; v.y *= m.y; v.z *= m.z; v.w *= m.w;
        out4[i] = v;
    }
}

// ---------------------------------------------------------------------------
// B2) Zero the 256 MB tail with streaming float4 stores (output is poisoned).
// ---------------------------------------------------------------------------
__global__ void zerotail_kernel(float4* __restrict__ out4, long long n4) {
    long long i = (long long)blockIdx.x * blockDim.x + threadIdx.x;
    long long stride = (long long)gridDim.x * blockDim.x;
    float4 z = make_float4(0.f, 0.f, 0.f, 0.f);
    for (; i < n4; i += stride) __stcs(out4 + i, z);
}

// ---------------------------------------------------------------------------
// C) Stream-compaction scatter: exact order-preserving scan of cross flags,
//    tail[cumsum-1][k] = delta/2. Non-crossing writes are 0 into zeros -> skip.
// ---------------------------------------------------------------------------
__global__ void scatter_kernel(float* __restrict__ out) {
    __shared__ int warp_sums[32];

    int tid  = threadIdx.x;          // 1024 threads
    int lane = tid & 31;
    int warp = tid >> 5;
    int base = tid * 8;              // 8 flags per thread -> 8192

    int flags[8];
    int local = 0;
#pragma unroll
    for (int i = 0; i < 8; i++) {
        flags[i] = g_flag[base + i];
        local += flags[i];
    }

    int v = local;
#pragma unroll
    for (int off = 1; off < 32; off <<= 1) {
        int n = __shfl_up_sync(0xffffffffu, v, off);
        if (lane >= off) v += n;
    }
    if (lane == 31) warp_sums[warp] = v;
    __syncthreads();

    if (warp == 0) {
        int w = warp_sums[lane];
#pragma unroll
        for (int off = 1; off < 32; off <<= 1) {
            int n = __shfl_up_sync(0xffffffffu, w, off);
            if (lane >= off) w += n;
        }
        warp_sums[lane] = w;
    }
    __syncthreads();

    int excl = (v - local) + (warp > 0 ? warp_sums[warp - 1] : 0);

    float* tail = out + (long long)E_ROWS * N_CONTENT;
    int row = excl;
#pragma unroll
    for (int i = 0; i < 8; i++) {
        int k = base + i;
        if (flags[i]) {
            int r = min(row, N_CONTENT - 1);
            tail[(long long)r * N_CONTENT + k] = g_val[k];
            row++;
        }
    }
}

// ---------------------------------------------------------------------------
extern "C" void kernel_launch(void* const* d_in, const int* in_sizes, int n_in,
                              void* d_out, int out_size) {
    const float* x = (const float*)d_in[0];
    float* out = (float*)d_out;

    // A) per-k scalars
    precompute_kernel<<<(N_CONTENT + 255) / 256, 256>>>(x);

    // B1) head+body: 64 rows x 2048 float4 = 131072 float4s, one per thread
    headbody_kernel<<<(E_ROWS * N_COL4) / 256, 256>>>((const float4*)x, (float4*)out);

    // B2) tail zeros: 8192 x 8192 floats = 16,777,216 float4s
    long long tail4 = (long long)N_CONTENT * N_CONTENT / 4;
    float4* tail = (float4*)(out + (long long)E_ROWS * N_CONTENT);
    zerotail_kernel<<<8192, 256>>>(tail, tail4);

    // C) scatter compacted tail values
    scatter_kernel<<<1, 1024>>>(out);
}